// round 3
// baseline (speedup 1.0000x reference)
#include <cuda_runtime.h>

#define OMEGA0 30.0f
#define HDIM 32
#define PADD 36                 // padded d-stride (floats): 144B lane stride, LDS.128 conflict-free
#define KSTRIDE (HDIM * PADD)   // 1152 floats per k-slice

// SMEM: W3s [32][32][36] + W2s [32*32] + W1s [32]
#define SMEM_FLOATS (32 * KSTRIDE + 1024 + 32)

__global__ __launch_bounds__(320, 1)
void ckconv_side_kernel(const float* __restrict__ emb,     // [N, 32] gathered embedding table
                        const float* __restrict__ t_node,  // [N]     node times
                        const float* __restrict__ edges_t, // [E]
                        const int*   __restrict__ gidx,    // [E] gather index
                        const int*   __restrict__ sidx,    // [E] segment index (other side)
                        const float* __restrict__ W1,      // [32]
                        const float* __restrict__ W2,      // [32,32]
                        const float* __restrict__ W3,      // [32,1024]
                        float*       __restrict__ out,     // [Nseg, 32]
                        int E)
{
    extern __shared__ float sm[];
    float* W3s = sm;                      // 32*1152
    float* W2s = sm + 32 * KSTRIDE;       // 1024
    float* W1s = W2s + 1024;              // 32

    const int tid = threadIdx.x;

    // Stage weights. W3 row-major [k, j=h*32+d] -> padded [k][h][d]
    for (int j = tid; j < 32 * 1024; j += blockDim.x) {
        int k = j >> 10;
        int r = j & 1023;
        int h = r >> 5;
        int d = r & 31;
        W3s[k * KSTRIDE + h * PADD + d] = W3[j];
    }
    for (int j = tid; j < 1024; j += blockDim.x) W2s[j] = W2[j];
    if (tid < 32) W1s[tid] = W1[tid];
    __syncthreads();

    const int lane    = tid & 31;
    const int gwarp   = blockIdx.x * (blockDim.x >> 5) + (tid >> 5);
    const int nwarps  = gridDim.x * (blockDim.x >> 5);
    const int ngroups = (E + 3) >> 2;     // 4 edges per warp-iteration

    const float  w1j  = W1s[lane];
    const float4* emb4 = reinterpret_cast<const float4*>(emb);

    #pragma unroll 1
    for (int p = gwarp; p < ngroups; p += nwarps) {
        const int eb = 4 * p;

        int   g[4], s[4];
        float t[4];
        #pragma unroll
        for (int e = 0; e < 4; e++) {
            const int ee = (eb + e < E) ? (eb + e) : eb;   // clamp tail (uniform per warp)
            g[e] = gidx[ee];
            s[e] = sidx[ee];
            t[e] = t_node[g[e]] - edges_t[ee];
        }

        // Gathered embeddings, broadcast-loaded into registers (4 x 32 floats)
        float4 em[4][8];
        #pragma unroll
        for (int e = 0; e < 4; e++)
            #pragma unroll
            for (int i = 0; i < 8; i++)
                em[e][i] = emb4[(size_t)g[e] * 8 + i];

        // Layer 1: lane j owns channel j
        float h1_[4];
        #pragma unroll
        for (int e = 0; e < 4; e++) h1_[e] = sinf(OMEGA0 * t[e] * w1j);

        // Layer 2: h2[j] = sin(omega * dot(h1, W2[:, j]))
        float acc[4] = {0.f, 0.f, 0.f, 0.f};
        #pragma unroll
        for (int k = 0; k < 32; k++) {
            const float w = W2s[k * 32 + lane];    // consecutive lanes -> conflict-free
            #pragma unroll
            for (int e = 0; e < 4; e++)
                acc[e] = fmaf(__shfl_sync(0xffffffffu, h1_[e], k), w, acc[e]);
        }
        float h2_[4];
        #pragma unroll
        for (int e = 0; e < 4; e++) h2_[e] = sinf(OMEGA0 * acc[e]);

        // Layer 3 fused with einsum: msg[h=lane] = sum_k h2[k] * sum_d W3[k][h][d]*emb[d]
        // Each LDS.128 of W3 feeds 16 FMAs (4 elems x 4 edges).
        float m[4] = {0.f, 0.f, 0.f, 0.f};
        #pragma unroll 2
        for (int k = 0; k < 32; k += 2) {
            float ca[4], cb[4];
            #pragma unroll
            for (int e = 0; e < 4; e++) {
                ca[e] = __shfl_sync(0xffffffffu, h2_[e], k);
                cb[e] = __shfl_sync(0xffffffffu, h2_[e], k + 1);
            }
            const float4* wka = reinterpret_cast<const float4*>(W3s + k * KSTRIDE + lane * PADD);
            const float4* wkb = reinterpret_cast<const float4*>(W3s + (k + 1) * KSTRIDE + lane * PADD);

            float da[4] = {0.f, 0.f, 0.f, 0.f};
            #pragma unroll
            for (int q = 0; q < 8; q++) {
                const float4 w = wka[q];
                #pragma unroll
                for (int e = 0; e < 4; e++)
                    da[e] += w.x * em[e][q].x + w.y * em[e][q].y
                           + w.z * em[e][q].z + w.w * em[e][q].w;
            }
            float db[4] = {0.f, 0.f, 0.f, 0.f};
            #pragma unroll
            for (int q = 0; q < 8; q++) {
                const float4 w = wkb[q];
                #pragma unroll
                for (int e = 0; e < 4; e++)
                    db[e] += w.x * em[e][q].x + w.y * em[e][q].y
                           + w.z * em[e][q].z + w.w * em[e][q].w;
            }
            #pragma unroll
            for (int e = 0; e < 4; e++)
                m[e] = fmaf(ca[e], da[e], fmaf(cb[e], db[e], m[e]));
        }

        #pragma unroll
        for (int e = 0; e < 4; e++)
            if (eb + e < E)
                atomicAdd(&out[(size_t)s[e] * 32 + lane], m[e]);
    }
}

extern "C" void kernel_launch(void* const* d_in, const int* in_sizes, int n_in,
                              void* d_out, int out_size)
{
    const float* u_emb   = (const float*)d_in[0];   // [U,32]
    const float* i_emb   = (const float*)d_in[1];   // [I,32]
    const int*   upt     = (const int*)  d_in[2];   // [E]
    const int*   ipt     = (const int*)  d_in[3];   // [E]
    const float* edges_t = (const float*)d_in[4];   // [E]
    const float* u_t     = (const float*)d_in[5];   // [U]
    const float* i_t     = (const float*)d_in[6];   // [I]
    const float* Wu1     = (const float*)d_in[7];
    const float* Wu2     = (const float*)d_in[8];
    const float* Wu3     = (const float*)d_in[9];
    const float* Wi1     = (const float*)d_in[10];
    const float* Wi2     = (const float*)d_in[11];
    const float* Wi3     = (const float*)d_in[12];

    const int E = in_sizes[4];
    const int U = in_sizes[5];

    float* out = (float*)d_out;

    const size_t smem = SMEM_FLOATS * sizeof(float);
    cudaFuncSetAttribute(ckconv_side_kernel,
                         cudaFuncAttributeMaxDynamicSharedMemorySize, (int)smem);

    // Output is poisoned; segment-sum accumulates -> zero it first.
    cudaMemsetAsync(d_out, 0, (size_t)out_size * sizeof(float));

    const int grid = 148;     // 1 block/SM (151.7 KB smem)
    const int threads = 320;  // 10 warps; ~175 regs/thread for 4-edge tiling

    // hLu: item kernels applied to i_embedded[item], segment-summed by user index.
    ckconv_side_kernel<<<grid, threads, smem>>>(
        i_emb, i_t, edges_t, ipt, upt, Wi1, Wi2, Wi3, out, E);

    // hLi: user kernels applied to u_embedded[user], summed by item index.
    ckconv_side_kernel<<<grid, threads, smem>>>(
        u_emb, u_t, edges_t, upt, ipt, Wu1, Wu2, Wu3, out + (size_t)U * 32, E);
}

// round 4
// speedup vs baseline: 1.1412x; 1.1412x over previous
#include <cuda_runtime.h>

#define OMEGA0 30.0f
#define HDIM 32
#define PADD 36                 // padded d-stride (floats): conflict-free LDS.128 (bank = 4l+4q over 8-lane phase)
#define KSTRIDE (HDIM * PADD)   // 1152 floats per k-slice

// SMEM: W3s [32][32][36] + W2s [32*32] + W1s [32]
#define SMEM_FLOATS (32 * KSTRIDE + 1024 + 32)

__global__ __launch_bounds__(448, 1)
void ckconv_side_kernel(const float* __restrict__ emb,     // [N, 32]
                        const float* __restrict__ t_node,  // [N]
                        const float* __restrict__ edges_t, // [E]
                        const int*   __restrict__ gidx,    // [E]
                        const int*   __restrict__ sidx,    // [E]
                        const float* __restrict__ W1,      // [32]
                        const float* __restrict__ W2,      // [32,32]
                        const float* __restrict__ W3,      // [32,1024]
                        float*       __restrict__ out,     // [Nseg, 32]
                        int E)
{
    extern __shared__ float sm[];
    float* W3s = sm;                      // 32*1152
    float* W2s = sm + 32 * KSTRIDE;       // 1024
    float* W1s = W2s + 1024;              // 32

    const int tid = threadIdx.x;

    // Stage weights. W3 row-major [k, j=h*32+d] -> padded [k][h][d]
    for (int j = tid; j < 32 * 1024; j += blockDim.x) {
        int k = j >> 10;
        int r = j & 1023;
        int h = r >> 5;
        int d = r & 31;
        W3s[k * KSTRIDE + h * PADD + d] = W3[j];
    }
    for (int j = tid; j < 1024; j += blockDim.x) W2s[j] = W2[j];
    if (tid < 32) W1s[tid] = W1[tid];
    __syncthreads();

    const int lane    = tid & 31;
    const int gwarp   = blockIdx.x * (blockDim.x >> 5) + (tid >> 5);
    const int nwarps  = gridDim.x * (blockDim.x >> 5);
    const int dhalf   = gwarp & 1;        // which 16 dims of d this warp covers
    const int ngroups = (E + 3) >> 2;     // 4 edges per group; 2 warps per group (d-split)

    const float  w1j  = W1s[lane];
    const float4* emb4 = reinterpret_cast<const float4*>(emb);
    const int qbase   = dhalf * 4;        // float4 offset into embedding row

    #pragma unroll 1
    for (int p = (gwarp >> 1); p < ngroups; p += (nwarps >> 1)) {
        const int eb = 4 * p;

        int   g[4], s[4];
        float t[4];
        #pragma unroll
        for (int e = 0; e < 4; e++) {
            const int ee = (eb + e < E) ? (eb + e) : eb;   // clamp tail (uniform per warp)
            g[e] = gidx[ee];
            s[e] = sidx[ee];
            t[e] = t_node[g[e]] - edges_t[ee];
        }

        // This warp's half of the gathered embeddings: 4 edges x 16 dims (64 regs)
        float4 em[4][4];
        #pragma unroll
        for (int e = 0; e < 4; e++)
            #pragma unroll
            for (int i = 0; i < 4; i++)
                em[e][i] = emb4[(size_t)g[e] * 8 + qbase + i];

        // Layer 1 (full h per lane; duplicated across the d-split pair — cheap)
        float h1_[4];
        #pragma unroll
        for (int e = 0; e < 4; e++) h1_[e] = sinf(OMEGA0 * t[e] * w1j);

        // Layer 2: h2[lane] = sin(omega * dot(h1, W2[:, lane]))
        float acc[4] = {0.f, 0.f, 0.f, 0.f};
        #pragma unroll
        for (int k = 0; k < 32; k++) {
            const float w = W2s[k * 32 + lane];
            #pragma unroll
            for (int e = 0; e < 4; e++)
                acc[e] = fmaf(__shfl_sync(0xffffffffu, h1_[e], k), w, acc[e]);
        }
        float h2_[4];
        #pragma unroll
        for (int e = 0; e < 4; e++) h2_[e] = sinf(OMEGA0 * acc[e]);

        // Layer 3, d-half partial: m[e] = sum_k h2[k] * sum_{d in half} W3[k][lane][d]*emb[d]
        // Each LDS.128 (this warp loads 16 floats of W3 per k) feeds 16 FMAs.
        float m[4] = {0.f, 0.f, 0.f, 0.f};
        const float* W3base = W3s + lane * PADD + dhalf * 16;
        #pragma unroll 2
        for (int k = 0; k < 32; k += 2) {
            float ca[4], cb[4];
            #pragma unroll
            for (int e = 0; e < 4; e++) {
                ca[e] = __shfl_sync(0xffffffffu, h2_[e], k);
                cb[e] = __shfl_sync(0xffffffffu, h2_[e], k + 1);
            }
            const float4* wka = reinterpret_cast<const float4*>(W3base + k * KSTRIDE);
            const float4* wkb = reinterpret_cast<const float4*>(W3base + (k + 1) * KSTRIDE);

            float da[4] = {0.f, 0.f, 0.f, 0.f};
            #pragma unroll
            for (int q = 0; q < 4; q++) {
                const float4 w = wka[q];
                #pragma unroll
                for (int e = 0; e < 4; e++)
                    da[e] += w.x * em[e][q].x + w.y * em[e][q].y
                           + w.z * em[e][q].z + w.w * em[e][q].w;
            }
            float db[4] = {0.f, 0.f, 0.f, 0.f};
            #pragma unroll
            for (int q = 0; q < 4; q++) {
                const float4 w = wkb[q];
                #pragma unroll
                for (int e = 0; e < 4; e++)
                    db[e] += w.x * em[e][q].x + w.y * em[e][q].y
                           + w.z * em[e][q].z + w.w * em[e][q].w;
            }
            #pragma unroll
            for (int e = 0; e < 4; e++)
                m[e] = fmaf(ca[e], da[e], fmaf(cb[e], db[e], m[e]));
        }

        // Each d-half warp contributes its partial independently (no pair sync).
        #pragma unroll
        for (int e = 0; e < 4; e++)
            if (eb + e < E)
                atomicAdd(&out[(size_t)s[e] * 32 + lane], m[e]);
    }
}

extern "C" void kernel_launch(void* const* d_in, const int* in_sizes, int n_in,
                              void* d_out, int out_size)
{
    const float* u_emb   = (const float*)d_in[0];   // [U,32]
    const float* i_emb   = (const float*)d_in[1];   // [I,32]
    const int*   upt     = (const int*)  d_in[2];   // [E]
    const int*   ipt     = (const int*)  d_in[3];   // [E]
    const float* edges_t = (const float*)d_in[4];   // [E]
    const float* u_t     = (const float*)d_in[5];   // [U]
    const float* i_t     = (const float*)d_in[6];   // [I]
    const float* Wu1     = (const float*)d_in[7];
    const float* Wu2     = (const float*)d_in[8];
    const float* Wu3     = (const float*)d_in[9];
    const float* Wi1     = (const float*)d_in[10];
    const float* Wi2     = (const float*)d_in[11];
    const float* Wi3     = (const float*)d_in[12];

    const int E = in_sizes[4];
    const int U = in_sizes[5];

    float* out = (float*)d_out;

    const size_t smem = SMEM_FLOATS * sizeof(float);
    cudaFuncSetAttribute(ckconv_side_kernel,
                         cudaFuncAttributeMaxDynamicSharedMemorySize, (int)smem);

    // Output is poisoned; segment-sum accumulates -> zero it first.
    cudaMemsetAsync(d_out, 0, (size_t)out_size * sizeof(float));

    const int grid = 148;     // 1 block/SM (151.7 KB smem)
    const int threads = 448;  // 14 warps; d-split keeps regs <= ~146

    // hLu: item kernels applied to i_embedded[item], segment-summed by user index.
    ckconv_side_kernel<<<grid, threads, smem>>>(
        i_emb, i_t, edges_t, ipt, upt, Wi1, Wi2, Wi3, out, E);

    // hLi: user kernels applied to u_embedded[user], summed by item index.
    ckconv_side_kernel<<<grid, threads, smem>>>(
        u_emb, u_t, edges_t, upt, ipt, Wu1, Wu2, Wu3, out + (size_t)U * 32, E);
}

// round 5
// speedup vs baseline: 3.8425x; 3.3671x over previous
#include <cuda_runtime.h>
#include <cuda_bf16.h>
#include <cstdint>

#define OMEGA0 30.0f
#define FULLMASK 0xffffffffu

// SMEM layout (bytes):
//   [0, 131072)             : W3 b-fragments, bf16 hi/lo, frag-ordered
//                             offset(k,c,t,part) = k*4096 + c*2048 + t*512 + part*256, 32 x uint2 slots
//   [131072, +4096)         : W2s (1024 f32)
//   [+4096, +128)           : W1s (32 f32)
//   then per-warp h2 scratch: 16 warps x 544 f32 (16 rows x stride 34)
#define BSM_BYTES   131072
#define NWARPS      16
#define H2_STRIDE   34
#define H2_PER_WARP (16 * H2_STRIDE)            // 544 floats
#define SMEM_BYTES  (BSM_BYTES + 4096 + 128 + NWARPS * H2_PER_WARP * 4)

__device__ __forceinline__ void split_bf16(float2 p, uint32_t& hi, uint32_t& lo)
{
    __nv_bfloat162 h = __float22bfloat162_rn(p);
    float2 hf = __bfloat1622float2(h);
    float2 r = make_float2(p.x - hf.x, p.y - hf.y);
    __nv_bfloat162 l = __float22bfloat162_rn(r);
    hi = *reinterpret_cast<uint32_t*>(&h);
    lo = *reinterpret_cast<uint32_t*>(&l);
}

__device__ __forceinline__ void mma_bf16(float& d0, float& d1, float& d2, float& d3,
                                         uint32_t a0, uint32_t a1, uint32_t a2, uint32_t a3,
                                         uint32_t b0, uint32_t b1,
                                         float c0, float c1, float c2, float c3)
{
    asm volatile("mma.sync.aligned.m16n8k16.row.col.f32.bf16.bf16.f32 "
                 "{%0,%1,%2,%3}, {%4,%5,%6,%7}, {%8,%9}, {%10,%11,%12,%13};"
                 : "=f"(d0), "=f"(d1), "=f"(d2), "=f"(d3)
                 : "r"(a0), "r"(a1), "r"(a2), "r"(a3), "r"(b0), "r"(b1),
                   "f"(c0), "f"(c1), "f"(c2), "f"(c3));
}

__global__ __launch_bounds__(512, 1)
void ckconv_side_kernel(const float* __restrict__ emb,     // [N, 32]
                        const float* __restrict__ t_node,  // [N]
                        const float* __restrict__ edges_t, // [E]
                        const int*   __restrict__ gidx,    // [E]
                        const int*   __restrict__ sidx,    // [E]
                        const float* __restrict__ W1,      // [32]
                        const float* __restrict__ W2,      // [32,32]
                        const float* __restrict__ W3,      // [32,1024]
                        float*       __restrict__ out,     // [Nseg, 32]
                        int E)
{
    extern __shared__ char smem_raw[];
    float* W2s  = reinterpret_cast<float*>(smem_raw + BSM_BYTES);
    float* W1s  = W2s + 1024;
    float* h2b  = W1s + 32;

    const int tid  = threadIdx.x;
    const int lane = tid & 31;
    const int warp = tid >> 5;

    // ---- Prologue A: stage W3 as hi/lo bf16 fragments in frag order ----
    // slot id bits: i = id&31 (lane-slot), t = (id>>5)&3, c = (id>>7)&1, k = id>>8
    {
        const float2* w3p = reinterpret_cast<const float2*>(W3);
        for (int id = tid; id < 8192; id += 512) {
            const int i  = id & 31;
            const int t  = (id >> 5) & 3;
            const int c  = (id >> 7) & 1;
            const int k  = id >> 8;
            const int hp = i >> 2;
            const int q  = i & 3;
            // W3 flat index = k*1024 + (8t+hp)*32 + 16c + 2q  -> float2 index:
            const size_t b2 = (size_t)k * 512 + (8 * t + hp) * 16 + 8 * c + q;
            const float2 v01 = w3p[b2];        // B rows 2q, 2q+1      (b0)
            const float2 v89 = w3p[b2 + 4];    // B rows 8+2q, 9+2q    (b1)
            uint32_t h0, l0, h1, l1;
            split_bf16(v01, h0, l0);
            split_bf16(v89, h1, l1);
            char* base = smem_raw + (size_t)k * 4096 + c * 2048 + t * 512;
            reinterpret_cast<uint2*>(base)[i]       = make_uint2(h0, h1);   // hi part
            reinterpret_cast<uint2*>(base + 256)[i] = make_uint2(l0, l1);   // lo part
        }
        for (int j = tid; j < 1024; j += 512) W2s[j] = W2[j];
        if (tid < 32) W1s[tid] = W1[tid];
    }
    __syncthreads();

    float* h2w = h2b + warp * H2_PER_WARP;

    const int r0 = lane >> 2;        // D/A row group
    const int r1 = r0 + 8;
    const int q  = lane & 3;

    const int gwarp  = blockIdx.x * NWARPS + warp;
    const int nwarps = gridDim.x * NWARPS;
    const int ngroups = (E + 15) >> 4;

    const float w1j = W1s[lane];
    const float2* e2 = reinterpret_cast<const float2*>(emb);
    const float fz = 0.0f;

    #pragma unroll 1
    for (int p = gwarp; p < ngroups; p += nwarps) {
        const int eb = p << 4;

        // ---- gather edge meta (lanes 0-15 carry edges; dup on 16-31) ----
        int el = eb + (lane & 15);
        if (el >= E) el = eb;                       // clamp tail (masked at output)
        const int   gl = gidx[el];
        const int   sl = sidx[el];
        const float tl = t_node[gl] - edges_t[el];

        const int g_r0 = __shfl_sync(FULLMASK, gl, r0);
        const int g_r1 = __shfl_sync(FULLMASK, gl, r1);
        const int s_r0 = __shfl_sync(FULLMASK, sl, r0);
        const int s_r1 = __shfl_sync(FULLMASK, sl, r1);

        // ---- layers 1-2: h2[e][k] into per-warp scratch (lane = k) ----
        #pragma unroll
        for (int e = 0; e < 16; e++) {
            const float te = __shfl_sync(FULLMASK, tl, e);
            const float h1 = sinf(OMEGA0 * te * w1j);
            float acc = 0.f;
            #pragma unroll
            for (int kk = 0; kk < 32; kk++)
                acc = fmaf(__shfl_sync(FULLMASK, h1, kk), W2s[kk * 32 + lane], acc);
            h2w[e * H2_STRIDE + lane] = sinf(OMEGA0 * acc);
        }
        __syncwarp();

        // ---- A fragments: emb tile [16,32], hi/lo bf16, k-invariant ----
        uint32_t Ahi[2][4], Alo[2][4];
        #pragma unroll
        for (int c = 0; c < 2; c++) {
            const float2 p0 = e2[(size_t)g_r0 * 16 + c * 8 + q];
            const float2 p1 = e2[(size_t)g_r1 * 16 + c * 8 + q];
            const float2 p2 = e2[(size_t)g_r0 * 16 + c * 8 + 4 + q];
            const float2 p3 = e2[(size_t)g_r1 * 16 + c * 8 + 4 + q];
            split_bf16(p0, Ahi[c][0], Alo[c][0]);
            split_bf16(p1, Ahi[c][1], Alo[c][1]);
            split_bf16(p2, Ahi[c][2], Alo[c][2]);
            split_bf16(p3, Ahi[c][3], Alo[c][3]);
        }

        // ---- main loop: per k, G = emb @ W3_k (3-term split), scale by h2 ----
        float msg[4][4];
        #pragma unroll
        for (int t = 0; t < 4; t++)
            #pragma unroll
            for (int j = 0; j < 4; j++) msg[t][j] = 0.f;

        #pragma unroll 2
        for (int k = 0; k < 32; k++) {
            const float h2a = h2w[r0 * H2_STRIDE + k];
            const float h2bv = h2w[r1 * H2_STRIDE + k];
            const uint2* bk = reinterpret_cast<const uint2*>(smem_raw + (size_t)k * 4096);
            #pragma unroll
            for (int t = 0; t < 4; t++) {
                const uint2 bh0 = bk[t * 64 + lane];            // c=0 hi
                const uint2 bl0 = bk[t * 64 + 32 + lane];       // c=0 lo
                const uint2 bh1 = bk[256 + t * 64 + lane];      // c=1 hi
                const uint2 bl1 = bk[256 + t * 64 + 32 + lane]; // c=1 lo
                float d0, d1, d2, d3;
                mma_bf16(d0, d1, d2, d3, Ahi[0][0], Ahi[0][1], Ahi[0][2], Ahi[0][3],
                         bh0.x, bh0.y, fz, fz, fz, fz);
                mma_bf16(d0, d1, d2, d3, Alo[0][0], Alo[0][1], Alo[0][2], Alo[0][3],
                         bh0.x, bh0.y, d0, d1, d2, d3);
                mma_bf16(d0, d1, d2, d3, Ahi[0][0], Ahi[0][1], Ahi[0][2], Ahi[0][3],
                         bl0.x, bl0.y, d0, d1, d2, d3);
                mma_bf16(d0, d1, d2, d3, Ahi[1][0], Ahi[1][1], Ahi[1][2], Ahi[1][3],
                         bh1.x, bh1.y, d0, d1, d2, d3);
                mma_bf16(d0, d1, d2, d3, Alo[1][0], Alo[1][1], Alo[1][2], Alo[1][3],
                         bh1.x, bh1.y, d0, d1, d2, d3);
                mma_bf16(d0, d1, d2, d3, Ahi[1][0], Ahi[1][1], Ahi[1][2], Ahi[1][3],
                         bl1.x, bl1.y, d0, d1, d2, d3);
                msg[t][0] = fmaf(h2a,  d0, msg[t][0]);
                msg[t][1] = fmaf(h2a,  d1, msg[t][1]);
                msg[t][2] = fmaf(h2bv, d2, msg[t][2]);
                msg[t][3] = fmaf(h2bv, d3, msg[t][3]);
            }
        }

        // ---- scatter: msg[e,h], rows r0/r1, cols t*8 + 2q + {0,1} ----
        const bool v0 = (eb + r0) < E;
        const bool v1 = (eb + r1) < E;
        #pragma unroll
        for (int t = 0; t < 4; t++) {
            const int h = t * 8 + 2 * q;
            if (v0) {
                atomicAdd(out + (size_t)s_r0 * 32 + h,     msg[t][0]);
                atomicAdd(out + (size_t)s_r0 * 32 + h + 1, msg[t][1]);
            }
            if (v1) {
                atomicAdd(out + (size_t)s_r1 * 32 + h,     msg[t][2]);
                atomicAdd(out + (size_t)s_r1 * 32 + h + 1, msg[t][3]);
            }
        }
    }
}

extern "C" void kernel_launch(void* const* d_in, const int* in_sizes, int n_in,
                              void* d_out, int out_size)
{
    const float* u_emb   = (const float*)d_in[0];   // [U,32]
    const float* i_emb   = (const float*)d_in[1];   // [I,32]
    const int*   upt     = (const int*)  d_in[2];   // [E]
    const int*   ipt     = (const int*)  d_in[3];   // [E]
    const float* edges_t = (const float*)d_in[4];   // [E]
    const float* u_t     = (const float*)d_in[5];   // [U]
    const float* i_t     = (const float*)d_in[6];   // [I]
    const float* Wu1     = (const float*)d_in[7];
    const float* Wu2     = (const float*)d_in[8];
    const float* Wu3     = (const float*)d_in[9];
    const float* Wi1     = (const float*)d_in[10];
    const float* Wi2     = (const float*)d_in[11];
    const float* Wi3     = (const float*)d_in[12];

    const int E = in_sizes[4];
    const int U = in_sizes[5];

    float* out = (float*)d_out;

    cudaFuncSetAttribute(ckconv_side_kernel,
                         cudaFuncAttributeMaxDynamicSharedMemorySize, SMEM_BYTES);

    // Output is poisoned; segment-sum accumulates -> zero it first.
    cudaMemsetAsync(d_out, 0, (size_t)out_size * sizeof(float));

    const int grid = 148;
    const int threads = 512;

    // hLu: item kernels applied to i_embedded[item], segment-summed by user index.
    ckconv_side_kernel<<<grid, threads, SMEM_BYTES>>>(
        i_emb, i_t, edges_t, ipt, upt, Wi1, Wi2, Wi3, out, E);

    // hLi: user kernels applied to u_embedded[user], summed by item index.
    ckconv_side_kernel<<<grid, threads, SMEM_BYTES>>>(
        u_emb, u_t, edges_t, upt, ipt, Wu1, Wu2, Wu3, out + (size_t)U * 32, E);
}

// round 6
// speedup vs baseline: 9.2416x; 2.4051x over previous
#include <cuda_runtime.h>
#include <cuda_fp16.h>
#include <cuda_bf16.h>
#include <cstdint>

#define OMEGA0 30.0f
#define FULLMASK 0xffffffffu
#define NWARPS 16

// SMEM layout (bytes):
//   [0, 65536)        : W3 b-fragments, fp16 (hi only), frag-ordered:
//                       uint2 index = k*256 + c*128 + t*32 + lane
//   [65536, +2048)    : W2 b-fragments bf16 HI : uint2 index = (c*4+u)*32 + lane
//   [67584, +2048)    : W2 b-fragments bf16 LO
//   [69632, +128)     : W1 (32 f32)
#define W3F_BYTES 65536
#define W2F_HI    65536
#define W2F_LO    67584
#define W1S_OFF   69632
#define SMEM_BYTES (W1S_OFF + 128)

__device__ __forceinline__ void split_bf16(float2 p, uint32_t& hi, uint32_t& lo)
{
    __nv_bfloat162 h = __float22bfloat162_rn(p);
    float2 hf = __bfloat1622float2(h);
    __nv_bfloat162 l = __float22bfloat162_rn(make_float2(p.x - hf.x, p.y - hf.y));
    hi = *reinterpret_cast<uint32_t*>(&h);
    lo = *reinterpret_cast<uint32_t*>(&l);
}

__device__ __forceinline__ uint32_t to_h2(float2 p)
{
    __half2 h = __float22half2_rn(p);
    return *reinterpret_cast<uint32_t*>(&h);
}

__device__ __forceinline__ void mma_bf16(float& d0, float& d1, float& d2, float& d3,
                                         uint32_t a0, uint32_t a1, uint32_t a2, uint32_t a3,
                                         uint32_t b0, uint32_t b1,
                                         float c0, float c1, float c2, float c3)
{
    asm volatile("mma.sync.aligned.m16n8k16.row.col.f32.bf16.bf16.f32 "
                 "{%0,%1,%2,%3}, {%4,%5,%6,%7}, {%8,%9}, {%10,%11,%12,%13};"
                 : "=f"(d0), "=f"(d1), "=f"(d2), "=f"(d3)
                 : "r"(a0), "r"(a1), "r"(a2), "r"(a3), "r"(b0), "r"(b1),
                   "f"(c0), "f"(c1), "f"(c2), "f"(c3));
}

__device__ __forceinline__ void mma_f16(float& d0, float& d1, float& d2, float& d3,
                                        uint32_t a0, uint32_t a1, uint32_t a2, uint32_t a3,
                                        uint32_t b0, uint32_t b1,
                                        float c0, float c1, float c2, float c3)
{
    asm volatile("mma.sync.aligned.m16n8k16.row.col.f32.f16.f16.f32 "
                 "{%0,%1,%2,%3}, {%4,%5,%6,%7}, {%8,%9}, {%10,%11,%12,%13};"
                 : "=f"(d0), "=f"(d1), "=f"(d2), "=f"(d3)
                 : "r"(a0), "r"(a1), "r"(a2), "r"(a3), "r"(b0), "r"(b1),
                   "f"(c0), "f"(c1), "f"(c2), "f"(c3));
}

__global__ __launch_bounds__(512, 1)
void ckconv_side_kernel(const float* __restrict__ emb,     // [N, 32]
                        const float* __restrict__ t_node,  // [N]
                        const float* __restrict__ edges_t, // [E]
                        const int*   __restrict__ gidx,    // [E]
                        const int*   __restrict__ sidx,    // [E]
                        const float* __restrict__ W1,      // [32]
                        const float* __restrict__ W2,      // [32,32]
                        const float* __restrict__ W3,      // [32,1024]
                        float*       __restrict__ out,     // [Nseg, 32]
                        int E)
{
    extern __shared__ char smem_raw[];
    float* W1s = reinterpret_cast<float*>(smem_raw + W1S_OFF);

    const int tid  = threadIdx.x;
    const int lane = tid & 31;
    const int warp = tid >> 5;

    // ---- Prologue: stage W3 as fp16 b-fragments (hi only) ----
    {
        const float2* w3p = reinterpret_cast<const float2*>(W3);
        for (int id = tid; id < 8192; id += 512) {
            const int i = id & 31;
            const int t = (id >> 5) & 3;
            const int c = (id >> 7) & 1;
            const int k = id >> 8;
            const int hp = i >> 2;
            const int q  = i & 3;
            const size_t b2 = (size_t)k * 512 + (8 * t + hp) * 16 + 8 * c + q;
            const uint32_t b0 = to_h2(w3p[b2]);       // B rows 2q,2q+1
            const uint32_t b1 = to_h2(w3p[b2 + 4]);   // B rows 8+2q,9+2q
            reinterpret_cast<uint2*>(smem_raw)[(size_t)k * 256 + c * 128 + t * 32 + i] =
                make_uint2(b0, b1);
        }
        // W2 fragments, bf16 hi/lo
        for (int s = tid; s < 256; s += 512) {
            const int i = s & 31;
            const int u = (s >> 5) & 3;
            const int c = s >> 7;
            const int hp = i >> 2;
            const int q  = i & 3;
            const int n  = 8 * u + hp;
            const float x0 = W2[(16 * c + 2 * q) * 32 + n];
            const float x1 = W2[(16 * c + 2 * q + 1) * 32 + n];
            const float x2 = W2[(16 * c + 2 * q + 8) * 32 + n];
            const float x3 = W2[(16 * c + 2 * q + 9) * 32 + n];
            uint32_t h0, l0, h1, l1;
            split_bf16(make_float2(x0, x1), h0, l0);
            split_bf16(make_float2(x2, x3), h1, l1);
            reinterpret_cast<uint2*>(smem_raw + W2F_HI)[s] = make_uint2(h0, h1);
            reinterpret_cast<uint2*>(smem_raw + W2F_LO)[s] = make_uint2(l0, l1);
        }
        if (tid < 32) W1s[tid] = W1[tid];
    }
    __syncthreads();

    const int r0 = lane >> 2;        // row group (rows r0 / r0+8)
    const int r1 = r0 + 8;
    const int q  = lane & 3;

    const int gwarp   = blockIdx.x * NWARPS + warp;
    const int nwarps  = gridDim.x * NWARPS;
    const int ngroups = (E + 15) >> 4;

    const float2* e2   = reinterpret_cast<const float2*>(emb);
    const float2* W1s2 = reinterpret_cast<const float2*>(W1s);
    const uint2*  w2hi = reinterpret_cast<const uint2*>(smem_raw + W2F_HI);
    const uint2*  w2lo = reinterpret_cast<const uint2*>(smem_raw + W2F_LO);
    const float fz = 0.0f;

    #pragma unroll 1
    for (int p = gwarp; p < ngroups; p += nwarps) {
        const int eb = p << 4;

        // ---- edge meta (lanes 0-15 carry edges; duplicated on 16-31) ----
        int el = eb + (lane & 15);
        if (el >= E) el = eb;                       // clamp tail (masked at scatter)
        const int   gl = gidx[el];
        const int   sl = sidx[el];
        const float tl = t_node[gl] - edges_t[el];

        const int g_r0 = __shfl_sync(FULLMASK, gl, r0);
        const int g_r1 = __shfl_sync(FULLMASK, gl, r1);
        const int s_r0 = __shfl_sync(FULLMASK, sl, r0);
        const int s_r1 = __shfl_sync(FULLMASK, sl, r1);
        const float t0 = __shfl_sync(FULLMASK, tl, r0);
        const float t1 = __shfl_sync(FULLMASK, tl, r1);

        // ---- layer 1: H1[e,k] A-fragments. Lane covers rows r0/r1, col pairs 8j+2q ----
        float s0[8], s1[8];
        #pragma unroll
        for (int j = 0; j < 4; j++) {
            const float2 w1p = W1s2[4 * j + q];
            s0[2 * j]     = __sinf(OMEGA0 * t0 * w1p.x);
            s0[2 * j + 1] = __sinf(OMEGA0 * t0 * w1p.y);
            s1[2 * j]     = __sinf(OMEGA0 * t1 * w1p.x);
            s1[2 * j + 1] = __sinf(OMEGA0 * t1 * w1p.y);
        }
        uint32_t Ah[2][4], Al[2][4];
        #pragma unroll
        for (int c = 0; c < 2; c++) {
            split_bf16(make_float2(s0[4 * c],     s0[4 * c + 1]), Ah[c][0], Al[c][0]);
            split_bf16(make_float2(s1[4 * c],     s1[4 * c + 1]), Ah[c][1], Al[c][1]);
            split_bf16(make_float2(s0[4 * c + 2], s0[4 * c + 3]), Ah[c][2], Al[c][2]);
            split_bf16(make_float2(s1[4 * c + 2], s1[4 * c + 3]), Ah[c][3], Al[c][3]);
        }

        // ---- layer 2: acc = H1 @ W2 (bf16 3-term), then h2 = sin(omega*acc) ----
        float acc[4][4];
        #pragma unroll
        for (int u = 0; u < 4; u++)
            #pragma unroll
            for (int j = 0; j < 4; j++) acc[u][j] = fz;
        #pragma unroll
        for (int c = 0; c < 2; c++) {
            #pragma unroll
            for (int u = 0; u < 4; u++) {
                const uint2 bh = w2hi[(c * 4 + u) * 32 + lane];
                const uint2 bl = w2lo[(c * 4 + u) * 32 + lane];
                mma_bf16(acc[u][0], acc[u][1], acc[u][2], acc[u][3],
                         Ah[c][0], Ah[c][1], Ah[c][2], Ah[c][3], bh.x, bh.y,
                         acc[u][0], acc[u][1], acc[u][2], acc[u][3]);
                mma_bf16(acc[u][0], acc[u][1], acc[u][2], acc[u][3],
                         Al[c][0], Al[c][1], Al[c][2], Al[c][3], bh.x, bh.y,
                         acc[u][0], acc[u][1], acc[u][2], acc[u][3]);
                mma_bf16(acc[u][0], acc[u][1], acc[u][2], acc[u][3],
                         Ah[c][0], Ah[c][1], Ah[c][2], Ah[c][3], bl.x, bl.y,
                         acc[u][0], acc[u][1], acc[u][2], acc[u][3]);
            }
        }
        float h2v[4][4];
        #pragma unroll
        for (int u = 0; u < 4; u++)
            #pragma unroll
            for (int j = 0; j < 4; j++)
                h2v[u][j] = __sinf(OMEGA0 * acc[u][j]);

        // ---- A fragments for layer 3: emb tile [16,32] in fp16 ----
        uint32_t Ae[2][4];
        #pragma unroll
        for (int c = 0; c < 2; c++) {
            Ae[c][0] = to_h2(e2[(size_t)g_r0 * 16 + c * 8 + q]);
            Ae[c][1] = to_h2(e2[(size_t)g_r1 * 16 + c * 8 + q]);
            Ae[c][2] = to_h2(e2[(size_t)g_r0 * 16 + c * 8 + 4 + q]);
            Ae[c][3] = to_h2(e2[(size_t)g_r1 * 16 + c * 8 + 4 + q]);
        }

        // ---- main loop over k: G_k = emb @ W3_k (fp16), msg += h2[.,k] * G_k ----
        float msg[4][4];
        #pragma unroll
        for (int t = 0; t < 4; t++)
            #pragma unroll
            for (int j = 0; j < 4; j++) msg[t][j] = fz;

        #pragma unroll
        for (int k = 0; k < 32; k++) {
            const int u  = k >> 3;
            const int b  = k & 1;
            const int qs = (k & 7) >> 1;
            const int srcl = r0 * 4 + qs;
            const float h2a = __shfl_sync(FULLMASK, h2v[u][b],     srcl);
            const float h2b = __shfl_sync(FULLMASK, h2v[u][2 + b], srcl);
            const uint2* bk = reinterpret_cast<const uint2*>(smem_raw) + (size_t)k * 256;
            #pragma unroll
            for (int t = 0; t < 4; t++) {
                const uint2 b0 = bk[t * 32 + lane];        // c = 0
                const uint2 b1 = bk[128 + t * 32 + lane];  // c = 1
                float d0, d1, d2, d3;
                mma_f16(d0, d1, d2, d3, Ae[0][0], Ae[0][1], Ae[0][2], Ae[0][3],
                        b0.x, b0.y, fz, fz, fz, fz);
                mma_f16(d0, d1, d2, d3, Ae[1][0], Ae[1][1], Ae[1][2], Ae[1][3],
                        b1.x, b1.y, d0, d1, d2, d3);
                msg[t][0] = fmaf(h2a, d0, msg[t][0]);
                msg[t][1] = fmaf(h2a, d1, msg[t][1]);
                msg[t][2] = fmaf(h2b, d2, msg[t][2]);
                msg[t][3] = fmaf(h2b, d3, msg[t][3]);
            }
        }

        // ---- scatter ----
        const bool v0 = (eb + r0) < E;
        const bool v1 = (eb + r1) < E;
        #pragma unroll
        for (int t = 0; t < 4; t++) {
            const int h = t * 8 + 2 * q;
            if (v0) {
                atomicAdd(out + (size_t)s_r0 * 32 + h,     msg[t][0]);
                atomicAdd(out + (size_t)s_r0 * 32 + h + 1, msg[t][1]);
            }
            if (v1) {
                atomicAdd(out + (size_t)s_r1 * 32 + h,     msg[t][2]);
                atomicAdd(out + (size_t)s_r1 * 32 + h + 1, msg[t][3]);
            }
        }
    }
}

extern "C" void kernel_launch(void* const* d_in, const int* in_sizes, int n_in,
                              void* d_out, int out_size)
{
    const float* u_emb   = (const float*)d_in[0];   // [U,32]
    const float* i_emb   = (const float*)d_in[1];   // [I,32]
    const int*   upt     = (const int*)  d_in[2];   // [E]
    const int*   ipt     = (const int*)  d_in[3];   // [E]
    const float* edges_t = (const float*)d_in[4];   // [E]
    const float* u_t     = (const float*)d_in[5];   // [U]
    const float* i_t     = (const float*)d_in[6];   // [I]
    const float* Wu1     = (const float*)d_in[7];
    const float* Wu2     = (const float*)d_in[8];
    const float* Wu3     = (const float*)d_in[9];
    const float* Wi1     = (const float*)d_in[10];
    const float* Wi2     = (const float*)d_in[11];
    const float* Wi3     = (const float*)d_in[12];

    const int E = in_sizes[4];
    const int U = in_sizes[5];

    float* out = (float*)d_out;

    cudaFuncSetAttribute(ckconv_side_kernel,
                         cudaFuncAttributeMaxDynamicSharedMemorySize, SMEM_BYTES);

    // Output is poisoned; segment-sum accumulates -> zero it first.
    cudaMemsetAsync(d_out, 0, (size_t)out_size * sizeof(float));

    const int grid = 148;
    const int threads = 512;

    // hLu: item kernels applied to i_embedded[item], segment-summed by user index.
    ckconv_side_kernel<<<grid, threads, SMEM_BYTES>>>(
        i_emb, i_t, edges_t, ipt, upt, Wi1, Wi2, Wi3, out, E);

    // hLi: user kernels applied to u_embedded[user], summed by item index.
    ckconv_side_kernel<<<grid, threads, SMEM_BYTES>>>(
        u_emb, u_t, edges_t, upt, ipt, Wu1, Wu2, Wu3, out + (size_t)U * 32, E);
}